// round 6
// baseline (speedup 1.0000x reference)
#include <cuda_runtime.h>

// Problem constants (from reference: B=32, T=512, F=513, S=3)
#define BB     32
#define NPB    262656          // T*F = 512*513 triples per batch
#define BLKX   64              // blocks per batch -> 2048 total CTAs
#define NTHR   256
#define NBLK   (BB * BLKX)     // 2048

// Cost-matrix accumulators (spread atomics) + hierarchical completion counters.
// All zero at static init; finisher re-zeroes everything -> graph-replay safe.
__device__ float g_C[BB * 9];
__device__ unsigned int g_cnt_b[BB];   // per-batch: 64 contenders each
__device__ unsigned int g_cnt;         // global: 32 contenders

// Fused kernel. grid (BLKX, BB), block NTHR. Scalar loads, unroll x4:
// front-batches 24 LDG.32 per thread iteration for high MLP (R1-measured 6.6 TB/s).
__global__ void __launch_bounds__(NTHR) pil_fused_kernel(
    const float* __restrict__ est, const float* __restrict__ tgt,
    float* __restrict__ out)
{
    const int b = blockIdx.y;
    const float* __restrict__ e = est + (size_t)b * NPB * 3;
    const float* __restrict__ t = tgt + (size_t)b * NPB * 3;

    float acc[9];
#pragma unroll
    for (int k = 0; k < 9; k++) acc[k] = 0.0f;

    const int stride = BLKX * NTHR;   // 16384 threads per batch
    int n = blockIdx.x * NTHR + threadIdx.x;

    for (; n + 3 * stride < NPB; n += 4 * stride) {
#pragma unroll
        for (int u = 0; u < 4; u++) {
            const int m = n + u * stride;
            const float e0 = e[3 * m + 0], e1 = e[3 * m + 1], e2 = e[3 * m + 2];
            const float t0 = t[3 * m + 0], t1 = t[3 * m + 1], t2 = t[3 * m + 2];
            acc[0] += fabsf(e0 - t0); acc[1] += fabsf(e0 - t1); acc[2] += fabsf(e0 - t2);
            acc[3] += fabsf(e1 - t0); acc[4] += fabsf(e1 - t1); acc[5] += fabsf(e1 - t2);
            acc[6] += fabsf(e2 - t0); acc[7] += fabsf(e2 - t1); acc[8] += fabsf(e2 - t2);
        }
    }
    for (; n < NPB; n += stride) {
        const float e0 = e[3 * n + 0], e1 = e[3 * n + 1], e2 = e[3 * n + 2];
        const float t0 = t[3 * n + 0], t1 = t[3 * n + 1], t2 = t[3 * n + 2];
        acc[0] += fabsf(e0 - t0); acc[1] += fabsf(e0 - t1); acc[2] += fabsf(e0 - t2);
        acc[3] += fabsf(e1 - t0); acc[4] += fabsf(e1 - t1); acc[5] += fabsf(e1 - t2);
        acc[6] += fabsf(e2 - t0); acc[7] += fabsf(e2 - t1); acc[8] += fabsf(e2 - t2);
    }

    // Warp reduction (9 values).
#pragma unroll
    for (int off = 16; off > 0; off >>= 1) {
#pragma unroll
        for (int k = 0; k < 9; k++)
            acc[k] += __shfl_down_sync(0xFFFFFFFFu, acc[k], off);
    }

    // Block reduction across 8 warps.
    __shared__ float s_part[NTHR / 32][9];
    const int lane = threadIdx.x & 31;
    const int warp = threadIdx.x >> 5;
    if (lane == 0) {
#pragma unroll
        for (int k = 0; k < 9; k++) s_part[warp][k] = acc[k];
    }
    __syncthreads();

    if (threadIdx.x < 9) {
        float s = 0.0f;
#pragma unroll
        for (int w = 0; w < NTHR / 32; w++) s += s_part[w][threadIdx.x];
        atomicAdd(&g_C[b * 9 + threadIdx.x], s);   // 288 spread addresses, 64 adds each
    }

    // ---- hierarchical last-block-done ----
    __shared__ unsigned int s_islast;
    __threadfence();                                // order g_C adds before counters
    if (threadIdx.x == 0) {
        s_islast = 0;
        if (atomicAdd(&g_cnt_b[b], 1u) == BLKX - 1) {        // last block of batch b
            __threadfence();
            s_islast = (atomicAdd(&g_cnt, 1u) == BB - 1);    // last batch overall
        }
    }
    __syncthreads();
    if (!s_islast) return;

    // ---- finisher: permutation-min epilogue ----
    __shared__ float sC[BB * 9];
    const int tid = threadIdx.x;
    for (int ent = tid; ent < BB * 9; ent += NTHR)
        sC[ent] = __ldcg(&g_C[ent]) * (1.0f / (float)NPB);
    __syncthreads();

    if (tid < 32) {
        const float* c = &sC[tid * 9];
        // C[i][j] = c[i*3+j]; loss_p = (C[p0][0] + C[p1][1] + C[p2][2]) / 3
        float best = c[0] + c[4] + c[8];
        best = fminf(best, c[0] + c[7] + c[5]);
        best = fminf(best, c[3] + c[1] + c[8]);
        best = fminf(best, c[3] + c[7] + c[2]);
        best = fminf(best, c[6] + c[1] + c[5]);
        best = fminf(best, c[6] + c[4] + c[2]);
        best *= (1.0f / 3.0f);

#pragma unroll
        for (int off = 16; off > 0; off >>= 1)
            best += __shfl_down_sync(0xFFFFFFFFu, best, off);

        if (tid == 0) out[0] = best * (1.0f / (float)BB);
    }
    __syncthreads();

    // Reset ALL scratch for the next graph replay.
    for (int ent = tid; ent < BB * 9; ent += NTHR) g_C[ent] = 0.0f;
    if (tid < BB) g_cnt_b[tid] = 0u;
    if (tid == 0) g_cnt = 0u;
}

extern "C" void kernel_launch(void* const* d_in, const int* in_sizes, int n_in,
                              void* d_out, int out_size) {
    const float* est = (const float*)d_in[0];
    const float* tgt = (const float*)d_in[1];
    float* out = (float*)d_out;

    dim3 grid(BLKX, BB);
    pil_fused_kernel<<<grid, NTHR>>>(est, tgt, out);
}

// round 7
// speedup vs baseline: 1.0236x; 1.0236x over previous
#include <cuda_runtime.h>

// Problem constants (from reference: B=32, T=512, F=513, S=3)
#define BB     32
#define NPB    262656          // T*F = 512*513 triples per batch
#define BLKX   64              // blocks per batch -> 2048 total CTAs
#define NTHR   256
#define NBLK   (BB * BLKX)     // 2048

// Cost-matrix accumulators (spread atomics) + hierarchical completion counters.
// All zero at static init; finisher re-zeroes everything -> graph-replay safe.
__device__ float g_C[BB * 9];
__device__ unsigned int g_cnt_b[BB];   // per-batch: 64 contenders each
__device__ unsigned int g_cnt;         // global: 32 contenders

// Fused kernel. grid (BLKX, BB), block NTHR. Scalar loads, unroll x4:
// front-batches 24 LDG.32 per thread iteration for high MLP (R1-measured 6.6 TB/s).
__global__ void __launch_bounds__(NTHR) pil_fused_kernel(
    const float* __restrict__ est, const float* __restrict__ tgt,
    float* __restrict__ out)
{
    const int b = blockIdx.y;
    const float* __restrict__ e = est + (size_t)b * NPB * 3;
    const float* __restrict__ t = tgt + (size_t)b * NPB * 3;

    float acc[9];
#pragma unroll
    for (int k = 0; k < 9; k++) acc[k] = 0.0f;

    const int stride = BLKX * NTHR;   // 16384 threads per batch
    int n = blockIdx.x * NTHR + threadIdx.x;

    for (; n + 3 * stride < NPB; n += 4 * stride) {
#pragma unroll
        for (int u = 0; u < 4; u++) {
            const int m = n + u * stride;
            const float e0 = e[3 * m + 0], e1 = e[3 * m + 1], e2 = e[3 * m + 2];
            const float t0 = t[3 * m + 0], t1 = t[3 * m + 1], t2 = t[3 * m + 2];
            acc[0] += fabsf(e0 - t0); acc[1] += fabsf(e0 - t1); acc[2] += fabsf(e0 - t2);
            acc[3] += fabsf(e1 - t0); acc[4] += fabsf(e1 - t1); acc[5] += fabsf(e1 - t2);
            acc[6] += fabsf(e2 - t0); acc[7] += fabsf(e2 - t1); acc[8] += fabsf(e2 - t2);
        }
    }
    for (; n < NPB; n += stride) {
        const float e0 = e[3 * n + 0], e1 = e[3 * n + 1], e2 = e[3 * n + 2];
        const float t0 = t[3 * n + 0], t1 = t[3 * n + 1], t2 = t[3 * n + 2];
        acc[0] += fabsf(e0 - t0); acc[1] += fabsf(e0 - t1); acc[2] += fabsf(e0 - t2);
        acc[3] += fabsf(e1 - t0); acc[4] += fabsf(e1 - t1); acc[5] += fabsf(e1 - t2);
        acc[6] += fabsf(e2 - t0); acc[7] += fabsf(e2 - t1); acc[8] += fabsf(e2 - t2);
    }

    // Warp reduction (9 values).
#pragma unroll
    for (int off = 16; off > 0; off >>= 1) {
#pragma unroll
        for (int k = 0; k < 9; k++)
            acc[k] += __shfl_down_sync(0xFFFFFFFFu, acc[k], off);
    }

    // Block reduction across 8 warps.
    __shared__ float s_part[NTHR / 32][9];
    const int lane = threadIdx.x & 31;
    const int warp = threadIdx.x >> 5;
    if (lane == 0) {
#pragma unroll
        for (int k = 0; k < 9; k++) s_part[warp][k] = acc[k];
    }
    __syncthreads();

    if (threadIdx.x < 9) {
        float s = 0.0f;
#pragma unroll
        for (int w = 0; w < NTHR / 32; w++) s += s_part[w][threadIdx.x];
        atomicAdd(&g_C[b * 9 + threadIdx.x], s);   // 288 spread addresses, 64 adds each
    }

    // ---- hierarchical last-block-done ----
    __shared__ unsigned int s_islast;
    __threadfence();                                // order g_C adds before counters
    if (threadIdx.x == 0) {
        s_islast = 0;
        if (atomicAdd(&g_cnt_b[b], 1u) == BLKX - 1) {        // last block of batch b
            __threadfence();
            s_islast = (atomicAdd(&g_cnt, 1u) == BB - 1);    // last batch overall
        }
    }
    __syncthreads();
    if (!s_islast) return;

    // ---- finisher: permutation-min epilogue ----
    __shared__ float sC[BB * 9];
    const int tid = threadIdx.x;
    for (int ent = tid; ent < BB * 9; ent += NTHR)
        sC[ent] = __ldcg(&g_C[ent]) * (1.0f / (float)NPB);
    __syncthreads();

    if (tid < 32) {
        const float* c = &sC[tid * 9];
        // C[i][j] = c[i*3+j]; loss_p = (C[p0][0] + C[p1][1] + C[p2][2]) / 3
        float best = c[0] + c[4] + c[8];
        best = fminf(best, c[0] + c[7] + c[5]);
        best = fminf(best, c[3] + c[1] + c[8]);
        best = fminf(best, c[3] + c[7] + c[2]);
        best = fminf(best, c[6] + c[1] + c[5]);
        best = fminf(best, c[6] + c[4] + c[2]);
        best *= (1.0f / 3.0f);

#pragma unroll
        for (int off = 16; off > 0; off >>= 1)
            best += __shfl_down_sync(0xFFFFFFFFu, best, off);

        if (tid == 0) out[0] = best * (1.0f / (float)BB);
    }
    __syncthreads();

    // Reset ALL scratch for the next graph replay.
    for (int ent = tid; ent < BB * 9; ent += NTHR) g_C[ent] = 0.0f;
    if (tid < BB) g_cnt_b[tid] = 0u;
    if (tid == 0) g_cnt = 0u;
}

extern "C" void kernel_launch(void* const* d_in, const int* in_sizes, int n_in,
                              void* d_out, int out_size) {
    const float* est = (const float*)d_in[0];
    const float* tgt = (const float*)d_in[1];
    float* out = (float*)d_out;

    dim3 grid(BLKX, BB);
    pil_fused_kernel<<<grid, NTHR>>>(est, tgt, out);
}